// round 5
// baseline (speedup 1.0000x reference)
#include <cuda_runtime.h>

#define BB 4
#define NN 8192
#define CC 64
#define OUTD 64
#define KNNK 36
#define BN (BB*NN)
#define KBLK 128
#define NSPLIT 2
#define HALF (NN/NSPLIT)       // 4096 candidates per split
#define TILE 256

// Device scratch (allocation-free rule: __device__ globals)
__device__ float4 g_xyz4[BN];             // (sq, x, y, z) packed per point
__device__ float  g_vfeat[BN*OUTD];       // relu([feature,xyz] @ W_v + b_v)
__device__ int    g_knn[BN*KNNK];         // final top-36 neighbor indices
__device__ float  g_pd[NSPLIT*BN*KNNK];   // partial top-36 distances
__device__ int    g_pi[NSPLIT*BN*KNNK];   // partial top-36 indices

// ---------------------------------------------------------------------------
__global__ void pack_xyz_kernel(const float* __restrict__ xyz) {
    int i = blockIdx.x * blockDim.x + threadIdx.x;
    if (i >= BN) return;
    float x = xyz[3*i], y = xyz[3*i+1], z = xyz[3*i+2];
    g_xyz4[i] = make_float4(x*x + y*y + z*z, x, y, z);
}

// ---------------------------------------------------------------------------
// v_feat = relu(concat([feature, xyz]) @ W_v + b_v)   (B,N,64)
// ---------------------------------------------------------------------------
__global__ __launch_bounds__(256) void vfeat_kernel(
    const float* __restrict__ feature,
    const float* __restrict__ xyz,
    const float* __restrict__ Wv,
    const float* __restrict__ bv)
{
    __shared__ float fsh[4][68];
    int sub = threadIdx.x >> 6;
    int t   = threadIdx.x & 63;
    int p   = blockIdx.x * 4 + sub;
    fsh[sub][t] = feature[p*64 + t];
    if (t < 3) fsh[sub][64 + t] = xyz[p*3 + t];
    __syncthreads();
    const float* f = fsh[sub];
    float acc = bv[t];
    #pragma unroll
    for (int c = 0; c < 67; c++)
        acc = fmaf(f[c], Wv[c*64 + t], acc);
    g_vfeat[p*64 + t] = fmaxf(acc, 0.0f);
}

// ---------------------------------------------------------------------------
// Exact 36-NN over HALF the candidates (blockIdx.y = half).
// Hot loop per 32 candidates: build a hit bitmask with NO stores and NO
// serial chains (FSETP+SEL+LOP3 OR-tree). Drain only on __any_sync hit,
// recomputing distances from the resident smem tile. worst is stale in the
// mask test (superset, exact recheck at drain) -> selection stays exact.
// ---------------------------------------------------------------------------
__device__ __forceinline__ void topk_insert(
    float d, int idx, float* kd, int* ki, float& worst, int& wpos)
{
    #pragma unroll
    for (int s = 0; s < KNNK; s++) {
        bool h = (s == wpos);
        kd[s] = h ? d   : kd[s];
        ki[s] = h ? idx : ki[s];
    }
    worst = kd[0]; wpos = 0;
    #pragma unroll
    for (int s = 1; s < KNNK; s++)
        if (kd[s] > worst) { worst = kd[s]; wpos = s; }
}

__global__ __launch_bounds__(KBLK) void knn_part_kernel() {
    __shared__ float4 tile[TILE];
    const unsigned FULL = 0xffffffffu;

    int tid = threadIdx.x;
    int q = blockIdx.x * KBLK + tid;     // global query index
    int h = blockIdx.y;                  // candidate half
    int b = q >> 13;

    float4 me = g_xyz4[q];
    float nx = -2.0f * me.y, ny = -2.0f * me.z, nz = -2.0f * me.w;

    float kd[KNNK];
    int   ki[KNNK];
    #pragma unroll
    for (int s = 0; s < KNNK; s++) { kd[s] = 3.4e38f; ki[s] = 0; }
    float worst = 3.4e38f;
    int   wpos  = 0;

    const float4* __restrict__ cand = g_xyz4 + b * NN + h * HALF;
    const int idx_off = h * HALF;

    for (int base = 0; base < HALF; base += TILE) {
        __syncthreads();
        tile[tid]        = cand[base + tid];
        tile[tid + KBLK] = cand[base + tid + KBLK];
        __syncthreads();

        #pragma unroll
        for (int js = 0; js < TILE; js += 32) {
            unsigned mask = 0;
            #pragma unroll
            for (int jj = 0; jj < 32; jj++) {
                float4 c = tile[js + jj];
                float d = fmaf(nx, c.y, c.x);
                d = fmaf(ny, c.z, d);
                d = fmaf(nz, c.w, d);
                mask |= (d < worst) ? (1u << jj) : 0u;
            }
            if (__any_sync(FULL, mask != 0u)) {
                while (mask) {
                    int jj = __ffs(mask) - 1;
                    mask &= mask - 1;
                    float4 c = tile[js + jj];
                    float d = fmaf(nx, c.y, c.x);
                    d = fmaf(ny, c.z, d);
                    d = fmaf(nz, c.w, d);
                    if (d < worst)
                        topk_insert(d, idx_off + base + js + jj, kd, ki, worst, wpos);
                }
            }
        }
    }

    size_t o = ((size_t)h * BN + q) * KNNK;
    #pragma unroll
    for (int s = 0; s < KNNK; s++) {
        g_pd[o + s] = kd[s];
        g_pi[o + s] = ki[s];
    }
}

// ---------------------------------------------------------------------------
// Merge: per query, exact top-36 of the union of the 2 partial top-36s.
// Both partial lists prefetched into registers (high MLP) before inserting.
// ---------------------------------------------------------------------------
__global__ __launch_bounds__(KBLK) void knn_merge_kernel() {
    int q = blockIdx.x * KBLK + threadIdx.x;

    float kd[KNNK];
    int   ki[KNNK];
    float pd1[KNNK];
    int   pi1[KNNK];

    size_t o0 = (size_t)q * KNNK;
    size_t o1 = ((size_t)BN + q) * KNNK;
    #pragma unroll
    for (int s = 0; s < KNNK; s++) {
        kd[s]  = g_pd[o0 + s];
        pd1[s] = g_pd[o1 + s];
    }
    #pragma unroll
    for (int s = 0; s < KNNK; s++) {
        ki[s]  = g_pi[o0 + s];
        pi1[s] = g_pi[o1 + s];
    }

    float worst = kd[0]; int wpos = 0;
    #pragma unroll
    for (int s = 1; s < KNNK; s++)
        if (kd[s] > worst) { worst = kd[s]; wpos = s; }

    #pragma unroll
    for (int it = 0; it < KNNK; it++) {
        if (pd1[it] < worst)
            topk_insert(pd1[it], pi1[it], kd, ki, worst, wpos);
    }

    #pragma unroll
    for (int s = 0; s < KNNK; s++)
        g_knn[(size_t)q * KNNK + s] = ki[s];
}

// ---------------------------------------------------------------------------
// Attention + suffix GEMM (coalesced row reads + shuffle reduce).
// ---------------------------------------------------------------------------
__global__ __launch_bounds__(256) void attn_kernel(
    const float* __restrict__ feature,
    const float* __restrict__ Wsuf,
    const float* __restrict__ bsuf,
    float* __restrict__ out)
{
    __shared__ float osh[8][64];
    const unsigned FULL = 0xffffffffu;
    int w    = threadIdx.x >> 5;
    int lane = threadIdx.x & 31;
    int p    = blockIdx.x * 8 + w;
    int b    = p >> 13;

    const float* frow = feature + (size_t)p * 64;
    float2 q2 = *(const float2*)(frow + 2*lane);

    int idxA = g_knn[p*KNNK + lane];
    int idxB = (lane < 4) ? g_knn[p*KNNK + 32 + lane] : 0;

    const float* fbase = feature + (size_t)b * NN * 64;
    float wA = 0.0f, wB = -3.4e38f;

    #pragma unroll
    for (int k = 0; k < KNNK; k++) {
        int j = (k < 32) ? __shfl_sync(FULL, idxA, k)
                         : __shfl_sync(FULL, idxB, k - 32);
        float2 f2 = *(const float2*)(fbase + (size_t)j * 64 + 2*lane);
        float part = fmaf(f2.x, q2.x, f2.y * q2.y);
        #pragma unroll
        for (int s = 16; s; s >>= 1)
            part += __shfl_xor_sync(FULL, part, s);
        if (k < 32) { if (lane == k)      wA = part; }
        else        { if (lane == k - 32) wB = part; }
    }

    float m = fmaxf(wA, (lane < 4) ? wB : -3.4e38f);
    #pragma unroll
    for (int s = 16; s; s >>= 1)
        m = fmaxf(m, __shfl_xor_sync(FULL, m, s));
    float eA = __expf(wA - m);
    float eB = (lane < 4) ? __expf(wB - m) : 0.0f;
    float ssum = eA + eB;
    #pragma unroll
    for (int s = 16; s; s >>= 1)
        ssum += __shfl_xor_sync(FULL, ssum, s);
    float inv = 1.0f / ssum;
    eA *= inv; eB *= inv;

    const float* vbase = g_vfeat + (size_t)b * NN * 64;
    float ox = 0.0f, oy = 0.0f;
    #pragma unroll
    for (int k = 0; k < KNNK; k++) {
        int j; float wk;
        if (k < 32) { j = __shfl_sync(FULL, idxA, k);      wk = __shfl_sync(FULL, eA, k); }
        else        { j = __shfl_sync(FULL, idxB, k - 32); wk = __shfl_sync(FULL, eB, k - 32); }
        float2 v2 = *(const float2*)(vbase + (size_t)j * 64 + 2*lane);
        ox = fmaf(wk, v2.x, ox);
        oy = fmaf(wk, v2.y, oy);
    }

    osh[w][2*lane]     = ox;
    osh[w][2*lane + 1] = oy;
    __syncwarp();
    float2 acc = *(const float2*)(bsuf + 2*lane);
    #pragma unroll 8
    for (int c = 0; c < 64; c++) {
        float oc = osh[w][c];
        float2 wv = *(const float2*)(Wsuf + c*64 + 2*lane);
        acc.x = fmaf(oc, wv.x, acc.x);
        acc.y = fmaf(oc, wv.y, acc.y);
    }
    *(float2*)(out + (size_t)p * 64 + 2*lane) = acc;
}

__global__ void tail_kernel(float* __restrict__ out, int out_size) {
    int i = BN*OUTD + blockIdx.x * blockDim.x + threadIdx.x;
    if (i < out_size) out[i] = (float)NN;
}

extern "C" void kernel_launch(void* const* d_in, const int* in_sizes, int n_in,
                              void* d_out, int out_size) {
    const float* feature = (const float*)d_in[0];
    const float* xyz     = (const float*)d_in[1];
    const float* Wv      = (const float*)d_in[2];
    const float* bv      = (const float*)d_in[3];
    const float* Wsuf    = (const float*)d_in[4];
    const float* bsuf    = (const float*)d_in[5];
    float* out = (float*)d_out;

    pack_xyz_kernel<<<(BN + 255) / 256, 256>>>(xyz);
    vfeat_kernel<<<BN / 4, 256>>>(feature, xyz, Wv, bv);
    dim3 kgrid(BN / KBLK, NSPLIT);
    knn_part_kernel<<<kgrid, KBLK>>>();
    knn_merge_kernel<<<BN / KBLK, KBLK>>>();
    attn_kernel<<<BN / 8, 256>>>(feature, Wsuf, bsuf, out);

    if (out_size > BN*OUTD) {
        int extra = out_size - BN*OUTD;
        tail_kernel<<<(extra + 255) / 256, 256>>>(out, out_size);
    }
}

// round 6
// speedup vs baseline: 1.2456x; 1.2456x over previous
#include <cuda_runtime.h>

#define BB 4
#define NN 8192
#define CC 64
#define OUTD 64
#define KNNK 36
#define BN (BB*NN)
#define KBLK 128
#define NSPLIT 4
#define QPART (NN/NSPLIT)      // 2048 candidates per split
#define TILE 256

// Device scratch (allocation-free rule: __device__ globals)
__device__ float4 g_xyz4[BN];             // (sq, x, y, z) packed per point
__device__ float  g_vfeat[BN*OUTD];       // relu([feature,xyz] @ W_v + b_v)
__device__ int    g_knn[BN*KNNK];         // final top-36 neighbor indices
__device__ float  g_pd[NSPLIT*BN*KNNK];   // partial top-36 distances
__device__ int    g_pi[NSPLIT*BN*KNNK];   // partial top-36 indices

// ---------------------------------------------------------------------------
__global__ void pack_xyz_kernel(const float* __restrict__ xyz) {
    int i = blockIdx.x * blockDim.x + threadIdx.x;
    if (i >= BN) return;
    float x = xyz[3*i], y = xyz[3*i+1], z = xyz[3*i+2];
    g_xyz4[i] = make_float4(x*x + y*y + z*z, x, y, z);
}

// ---------------------------------------------------------------------------
// v_feat = relu(concat([feature, xyz]) @ W_v + b_v)   (B,N,64)
// ---------------------------------------------------------------------------
__global__ __launch_bounds__(256) void vfeat_kernel(
    const float* __restrict__ feature,
    const float* __restrict__ xyz,
    const float* __restrict__ Wv,
    const float* __restrict__ bv)
{
    __shared__ float fsh[4][68];
    int sub = threadIdx.x >> 6;
    int t   = threadIdx.x & 63;
    int p   = blockIdx.x * 4 + sub;
    fsh[sub][t] = feature[p*64 + t];
    if (t < 3) fsh[sub][64 + t] = xyz[p*3 + t];
    __syncthreads();
    const float* f = fsh[sub];
    float acc = bv[t];
    #pragma unroll
    for (int c = 0; c < 67; c++)
        acc = fmaf(f[c], Wv[c*64 + t], acc);
    g_vfeat[p*64 + t] = fmaxf(acc, 0.0f);
}

// ---------------------------------------------------------------------------
// Equality-replace insert: replace slot(s) holding the current worst, then
// recompute worst via an FMNMX tree. No wpos tracking.
// ---------------------------------------------------------------------------
__device__ __forceinline__ void topk_insert_eq(
    float d, int idx, float* kd, int* ki, float& worst)
{
    #pragma unroll
    for (int s = 0; s < KNNK; s++) {
        bool h = (kd[s] == worst);
        kd[s] = h ? d   : kd[s];
        ki[s] = h ? idx : ki[s];
    }
    float w = kd[0];
    #pragma unroll
    for (int s = 1; s < KNNK; s++)
        w = fmaxf(w, kd[s]);
    worst = w;
}

// ---------------------------------------------------------------------------
// Exact 36-NN over a quarter of the candidates (blockIdx.y = split).
// - First 36 candidates fill the top-36 directly (no insert storm).
// - Hot loop: 32-candidate groups, 4 independent hit-mask accumulators
//   (no serial OR chain, no stores, no cnt chain).
// - Drain on __any_sync hit: recompute d from the resident smem tile,
//   exact recheck, equality-replace insert.
// ---------------------------------------------------------------------------
__global__ __launch_bounds__(KBLK) void knn_part_kernel() {
    __shared__ float4 tile[TILE];
    const unsigned FULL = 0xffffffffu;

    int tid = threadIdx.x;
    int q = blockIdx.x * KBLK + tid;     // global query index
    int h = blockIdx.y;                  // candidate quarter
    int b = q >> 13;

    float4 me = g_xyz4[q];
    float nx = -2.0f * me.y, ny = -2.0f * me.z, nz = -2.0f * me.w;

    float kd[KNNK];
    int   ki[KNNK];
    float worst;

    const float4* __restrict__ cand = g_xyz4 + b * NN + h * QPART;
    const int idx_off = h * QPART;

    for (int base = 0; base < QPART; base += TILE) {
        __syncthreads();
        tile[tid]        = cand[base + tid];
        tile[tid + KBLK] = cand[base + tid + KBLK];
        __syncthreads();

        int js_start = 0;
        if (base == 0) {
            // fill top-36 from candidates 0..35 directly
            #pragma unroll
            for (int s = 0; s < KNNK; s++) {
                float4 c = tile[s];
                float d = fmaf(nx, c.y, c.x);
                d = fmaf(ny, c.z, d);
                d = fmaf(nz, c.w, d);
                kd[s] = d;
                ki[s] = idx_off + s;
            }
            float w = kd[0];
            #pragma unroll
            for (int s = 1; s < KNNK; s++)
                w = fmaxf(w, kd[s]);
            worst = w;
            js_start = 32;   // group js=32 handles 32..63 (mask off 32..35)
        }

        for (int js = js_start; js < TILE; js += 32) {
            unsigned m0 = 0, m1 = 0, m2 = 0, m3 = 0;
            #pragma unroll
            for (int jj = 0; jj < 8; jj++) {
                float4 c = tile[js + jj];
                float d = fmaf(nx, c.y, c.x);
                d = fmaf(ny, c.z, d); d = fmaf(nz, c.w, d);
                m0 |= (d < worst) ? (1u << jj) : 0u;
            }
            #pragma unroll
            for (int jj = 8; jj < 16; jj++) {
                float4 c = tile[js + jj];
                float d = fmaf(nx, c.y, c.x);
                d = fmaf(ny, c.z, d); d = fmaf(nz, c.w, d);
                m1 |= (d < worst) ? (1u << jj) : 0u;
            }
            #pragma unroll
            for (int jj = 16; jj < 24; jj++) {
                float4 c = tile[js + jj];
                float d = fmaf(nx, c.y, c.x);
                d = fmaf(ny, c.z, d); d = fmaf(nz, c.w, d);
                m2 |= (d < worst) ? (1u << jj) : 0u;
            }
            #pragma unroll
            for (int jj = 24; jj < 32; jj++) {
                float4 c = tile[js + jj];
                float d = fmaf(nx, c.y, c.x);
                d = fmaf(ny, c.z, d); d = fmaf(nz, c.w, d);
                m3 |= (d < worst) ? (1u << jj) : 0u;
            }
            unsigned mask = (m0 | m1) | (m2 | m3);
            if (base == 0 && js == 32) mask &= 0xFFFFFFF0u;  // 32..35 filled

            if (__any_sync(FULL, mask != 0u)) {
                while (mask) {
                    int jj = __ffs(mask) - 1;
                    mask &= mask - 1;
                    float4 c = tile[js + jj];
                    float d = fmaf(nx, c.y, c.x);
                    d = fmaf(ny, c.z, d);
                    d = fmaf(nz, c.w, d);
                    if (d < worst)
                        topk_insert_eq(d, idx_off + base + js + jj, kd, ki, worst);
                }
            }
        }
    }

    size_t o = ((size_t)h * BN + q) * KNNK;
    #pragma unroll
    for (int s = 0; s < KNNK; s++) {
        g_pd[o + s] = kd[s];
        g_pi[o + s] = ki[s];
    }
}

// ---------------------------------------------------------------------------
// Merge: per query, exact top-36 of the union of NSPLIT partial top-36s.
// Prefetch each list's distances (vectorized); load indices lazily on insert.
// ---------------------------------------------------------------------------
__global__ __launch_bounds__(KBLK) void knn_merge_kernel() {
    int q = blockIdx.x * KBLK + threadIdx.x;

    float kd[KNNK];
    int   ki[KNNK];

    size_t o0 = (size_t)q * KNNK;
    #pragma unroll
    for (int s = 0; s < KNNK; s++) { kd[s] = g_pd[o0 + s]; ki[s] = g_pi[o0 + s]; }

    float worst = kd[0];
    #pragma unroll
    for (int s = 1; s < KNNK; s++)
        worst = fmaxf(worst, kd[s]);

    for (int hh = 1; hh < NSPLIT; hh++) {
        size_t oh = ((size_t)hh * BN + q) * KNNK;
        float pd[KNNK];
        const float4* pv = (const float4*)(g_pd + oh);
        #pragma unroll
        for (int v = 0; v < KNNK/4; v++) {
            float4 t = pv[v];
            pd[4*v] = t.x; pd[4*v+1] = t.y; pd[4*v+2] = t.z; pd[4*v+3] = t.w;
        }
        #pragma unroll
        for (int it = 0; it < KNNK; it++) {
            if (pd[it] < worst) {
                int idx = g_pi[oh + it];
                topk_insert_eq(pd[it], idx, kd, ki, worst);
            }
        }
    }

    #pragma unroll
    for (int s = 0; s < KNNK; s++)
        g_knn[(size_t)q * KNNK + s] = ki[s];
}

// ---------------------------------------------------------------------------
// Attention + suffix GEMM (coalesced row reads + shuffle reduce).
// ---------------------------------------------------------------------------
__global__ __launch_bounds__(256) void attn_kernel(
    const float* __restrict__ feature,
    const float* __restrict__ Wsuf,
    const float* __restrict__ bsuf,
    float* __restrict__ out)
{
    __shared__ float osh[8][64];
    const unsigned FULL = 0xffffffffu;
    int w    = threadIdx.x >> 5;
    int lane = threadIdx.x & 31;
    int p    = blockIdx.x * 8 + w;
    int b    = p >> 13;

    const float* frow = feature + (size_t)p * 64;
    float2 q2 = *(const float2*)(frow + 2*lane);

    int idxA = g_knn[p*KNNK + lane];
    int idxB = (lane < 4) ? g_knn[p*KNNK + 32 + lane] : 0;

    const float* fbase = feature + (size_t)b * NN * 64;
    float wA = 0.0f, wB = -3.4e38f;

    #pragma unroll
    for (int k = 0; k < KNNK; k++) {
        int j = (k < 32) ? __shfl_sync(FULL, idxA, k)
                         : __shfl_sync(FULL, idxB, k - 32);
        float2 f2 = *(const float2*)(fbase + (size_t)j * 64 + 2*lane);
        float part = fmaf(f2.x, q2.x, f2.y * q2.y);
        #pragma unroll
        for (int s = 16; s; s >>= 1)
            part += __shfl_xor_sync(FULL, part, s);
        if (k < 32) { if (lane == k)      wA = part; }
        else        { if (lane == k - 32) wB = part; }
    }

    float m = fmaxf(wA, (lane < 4) ? wB : -3.4e38f);
    #pragma unroll
    for (int s = 16; s; s >>= 1)
        m = fmaxf(m, __shfl_xor_sync(FULL, m, s));
    float eA = __expf(wA - m);
    float eB = (lane < 4) ? __expf(wB - m) : 0.0f;
    float ssum = eA + eB;
    #pragma unroll
    for (int s = 16; s; s >>= 1)
        ssum += __shfl_xor_sync(FULL, ssum, s);
    float inv = 1.0f / ssum;
    eA *= inv; eB *= inv;

    const float* vbase = g_vfeat + (size_t)b * NN * 64;
    float ox = 0.0f, oy = 0.0f;
    #pragma unroll
    for (int k = 0; k < KNNK; k++) {
        int j; float wk;
        if (k < 32) { j = __shfl_sync(FULL, idxA, k);      wk = __shfl_sync(FULL, eA, k); }
        else        { j = __shfl_sync(FULL, idxB, k - 32); wk = __shfl_sync(FULL, eB, k - 32); }
        float2 v2 = *(const float2*)(vbase + (size_t)j * 64 + 2*lane);
        ox = fmaf(wk, v2.x, ox);
        oy = fmaf(wk, v2.y, oy);
    }

    osh[w][2*lane]     = ox;
    osh[w][2*lane + 1] = oy;
    __syncwarp();
    float2 acc = *(const float2*)(bsuf + 2*lane);
    #pragma unroll 8
    for (int c = 0; c < 64; c++) {
        float oc = osh[w][c];
        float2 wv = *(const float2*)(Wsuf + c*64 + 2*lane);
        acc.x = fmaf(oc, wv.x, acc.x);
        acc.y = fmaf(oc, wv.y, acc.y);
    }
    *(float2*)(out + (size_t)p * 64 + 2*lane) = acc;
}

__global__ void tail_kernel(float* __restrict__ out, int out_size) {
    int i = BN*OUTD + blockIdx.x * blockDim.x + threadIdx.x;
    if (i < out_size) out[i] = (float)NN;
}

extern "C" void kernel_launch(void* const* d_in, const int* in_sizes, int n_in,
                              void* d_out, int out_size) {
    const float* feature = (const float*)d_in[0];
    const float* xyz     = (const float*)d_in[1];
    const float* Wv      = (const float*)d_in[2];
    const float* bv      = (const float*)d_in[3];
    const float* Wsuf    = (const float*)d_in[4];
    const float* bsuf    = (const float*)d_in[5];
    float* out = (float*)d_out;

    pack_xyz_kernel<<<(BN + 255) / 256, 256>>>(xyz);
    vfeat_kernel<<<BN / 4, 256>>>(feature, xyz, Wv, bv);
    dim3 kgrid(BN / KBLK, NSPLIT);
    knn_part_kernel<<<kgrid, KBLK>>>();
    knn_merge_kernel<<<BN / KBLK, KBLK>>>();
    attn_kernel<<<BN / 8, 256>>>(feature, Wsuf, bsuf, out);

    if (out_size > BN*OUTD) {
        int extra = out_size - BN*OUTD;
        tail_kernel<<<(extra + 255) / 256, 256>>>(out, out_size);
    }
}